// round 5
// baseline (speedup 1.0000x reference)
#include <cuda_runtime.h>
#include <math.h>

#define T_TOK 8192
#define D_IN  4096
#define D_OUT 4096
#define NPAIR 64
#define SPLITS 8
#define KSPL  512
#define KCH   64
#define BM    64
#define MAXT  192
#define RBLK  32          /* route blocks: 8192/256 */
#define SCALING 2.0f

/* ------------------ static device scratch (no allocation) ------------------ */
__device__ int    g_pairA[T_TOK];
__device__ float2 g_wA[T_TOK];
__device__ int    g_pairB[T_TOK];
__device__ float2 g_wB[T_TOK];
__device__ int g_cntA[NPAIR], g_cntB[NPAIR];
__device__ int g_curA[NPAIR], g_curB[NPAIR];
__device__ int g_listA[T_TOK], g_listB[T_TOK];
__device__ int g_tAp[MAXT], g_tAs[MAXT], g_tAc[MAXT];
__device__ int g_tBp[MAXT], g_tBs[MAXT], g_tBc[MAXT];
__device__ int g_nTA, g_nTB;
__device__ float g_psA[RBLK][8];
__device__ float g_psB[RBLK][8];
__device__ float g_raw[SPLITS][T_TOK][16];   /* stage-A split-K partials */
__device__ float g_v[T_TOK][16];             /* B-weighted, scaled mid  */

/* ------------------------------- kernel 0 --------------------------------- */
__global__ void k_zero() {
    int t = threadIdx.x;
    if (t < NPAIR) { g_cntA[t] = 0; g_cntB[t] = 0; }
}

/* ------------------------------- routing ---------------------------------- */
__device__ __forceinline__ void route_one(const float* __restrict__ lg, int t,
                                          int* pair, float2* w, int* cnt,
                                          float probs[8]) {
    const float4* p4 = (const float4*)lg + (size_t)t * 2;
    float4 a = p4[0], b = p4[1];
    float l[8] = {a.x, a.y, a.z, a.w, b.x, b.y, b.z, b.w};
    int i0 = 0; float v0 = l[0];
    #pragma unroll
    for (int i = 1; i < 8; i++) if (l[i] > v0) { v0 = l[i]; i0 = i; }
    int i1 = -1; float v1 = -3.0e38f;
    #pragma unroll
    for (int i = 0; i < 8; i++) if (i != i0 && l[i] > v1) { v1 = l[i]; i1 = i; }
    float e  = expf(v1 - v0);
    float w0 = 1.0f / (1.0f + e);
    float w1 = e * w0;
    int elo, ehi; float wlo, whi;
    if (i0 < i1) { elo = i0; ehi = i1; wlo = w0; whi = w1; }
    else         { elo = i1; ehi = i0; wlo = w1; whi = w0; }
    int pp = elo * 8 + ehi;
    pair[t] = pp;
    w[t] = make_float2(wlo, whi);
    atomicAdd(&cnt[pp], 1);
    float s = 0.0f;
    #pragma unroll
    for (int i = 0; i < 8; i++) { probs[i] = expf(l[i] - v0); s += probs[i]; }
    float inv = 1.0f / s;
    #pragma unroll
    for (int i = 0; i < 8; i++) probs[i] *= inv;
}

__global__ void __launch_bounds__(256) k_route(const float* __restrict__ rla,
                                               const float* __restrict__ rlb) {
    int tid = threadIdx.x;
    int t = blockIdx.x * 256 + tid;
    float pa[8], pb[8];
    route_one(rla, t, g_pairA, g_wA, g_cntA, pa);
    route_one(rlb, t, g_pairB, g_wB, g_cntB, pb);

    __shared__ float sA[8][8], sB[8][8];
    int warp = tid >> 5, lane = tid & 31;
    #pragma unroll
    for (int e = 0; e < 8; e++) {
        float s = pa[e];
        #pragma unroll
        for (int o = 16; o > 0; o >>= 1) s += __shfl_xor_sync(0xffffffffu, s, o);
        if (lane == 0) sA[warp][e] = s;
        float s2 = pb[e];
        #pragma unroll
        for (int o = 16; o > 0; o >>= 1) s2 += __shfl_xor_sync(0xffffffffu, s2, o);
        if (lane == 0) sB[warp][e] = s2;
    }
    __syncthreads();
    if (tid < 8) {
        float s = 0.0f;
        #pragma unroll
        for (int w2 = 0; w2 < 8; w2++) s += sA[w2][tid];
        g_psA[blockIdx.x][tid] = s;
    } else if (tid < 16) {
        int e = tid - 8; float s = 0.0f;
        #pragma unroll
        for (int w2 = 0; w2 < 8; w2++) s += sB[w2][e];
        g_psB[blockIdx.x][e] = s;
    }
}

/* ------------------------------ planning ---------------------------------- */
__global__ void k_plan(float* __restrict__ out, long long out_size) {
    int tid = threadIdx.x;
    if (tid == 0) {
        int off = 0, nt = 0;
        for (int p = 0; p < NPAIR; p++) {
            int c = g_cntA[p];
            g_curA[p] = off;
            int s = off;
            while (c > 0 && nt < MAXT) {
                g_tAp[nt] = p; g_tAs[nt] = s;
                g_tAc[nt] = (c < BM) ? c : BM;
                nt++; s += BM; c -= BM;
            }
            off += g_cntA[p];
        }
        g_nTA = nt;
    }
    if (tid == 32) {
        int off = 0, nt = 0;
        for (int p = 0; p < NPAIR; p++) {
            int c = g_cntB[p];
            g_curB[p] = off;
            int s = off;
            while (c > 0 && nt < MAXT) {
                g_tBp[nt] = p; g_tBs[nt] = s;
                g_tBc[nt] = (c < BM) ? c : BM;
                nt++; s += BM; c -= BM;
            }
            off += g_cntB[p];
        }
        g_nTB = nt;
    }
    if (tid == 64 && out_size >= (long long)T_TOK * D_OUT + 2) {
        float pr[8];
        for (int e = 0; e < 8; e++) {
            float s = 0.0f;
            for (int b = 0; b < RBLK; b++) s += g_psA[b][e];
            pr[e] = s / (float)T_TOK;
        }
        float m = 0.0f;
        for (int e = 0; e < 8; e++) m += pr[e];
        m *= 0.125f;
        float v = 0.0f;
        for (int e = 0; e < 8; e++) { float d = pr[e] - m; v += d * d; }
        out[out_size - 2] = 8.0f * (v / 7.0f);
    }
    if (tid == 96 && out_size >= (long long)T_TOK * D_OUT + 2) {
        float pr[8];
        for (int e = 0; e < 8; e++) {
            float s = 0.0f;
            for (int b = 0; b < RBLK; b++) s += g_psB[b][e];
            pr[e] = s / (float)T_TOK;
        }
        float m = 0.0f;
        for (int e = 0; e < 8; e++) m += pr[e];
        m *= 0.125f;
        float v = 0.0f;
        for (int e = 0; e < 8; e++) { float d = pr[e] - m; v += d * d; }
        out[out_size - 1] = 8.0f * (v / 7.0f);
    }
}

/* ------------------------------ scatter ----------------------------------- */
__global__ void __launch_bounds__(256) k_scatter() {
    int t = blockIdx.x * 256 + threadIdx.x;
    int s1 = atomicAdd(&g_curA[g_pairA[t]], 1);
    g_listA[s1] = t;
    int s2 = atomicAdd(&g_curB[g_pairB[t]], 1);
    g_listB[s2] = t;
}

/* ------------------------------ GEMM A ------------------------------------ */
/* grid (MAXT, SPLITS), 32 threads. tile: 64 tokens x 16 rows, K split of 512 */
#define XS_STRIDE 69
__global__ void __launch_bounds__(32) k_gemmA(const float* __restrict__ x,
                                              const float* __restrict__ Wa) {
    int tile = blockIdx.x;
    if (tile >= g_nTA) return;
    int split = blockIdx.y;
    int p = g_tAp[tile], base = g_tAs[tile], cnt = g_tAc[tile];
    int elo = p >> 3, ehi = p & 7;

    __shared__ float xs[64 * XS_STRIDE];
    __shared__ float ws[16 * XS_STRIDE];
    __shared__ int   toks[64];

    int tid = threadIdx.x;
    int jIdx = tid & 3;        /* 4 output-groups of 4    */
    int tmIdx = tid >> 2;      /* 8 token-groups of 8     */

    /* token ids */
    {
        int s0 = tid, s1 = tid + 32;
        toks[s0] = g_listA[base + ((s0 < cnt) ? s0 : 0)];
        toks[s1] = g_listA[base + ((s1 < cnt) ? s1 : 0)];
    }
    __syncwarp();

    float acc[8][4];
    #pragma unroll
    for (int i = 0; i < 8; i++)
        #pragma unroll
        for (int j = 0; j < 4; j++) acc[i][j] = 0.0f;

    int kBase = split * KSPL;
    for (int ch = 0; ch < KSPL / KCH; ch++) {
        int k0 = kBase + ch * KCH;
        /* load x chunk: 64 rows x 64 cols = 1024 float4, 32/thread */
        #pragma unroll
        for (int it = 0; it < 32; it++) {
            int idx = tid + 32 * it;
            int row = idx >> 4, c = idx & 15;
            float4 v = *(const float4*)(x + (size_t)toks[row] * D_IN + k0 + 4 * c);
            float* d = &xs[row * XS_STRIDE + 4 * c];
            d[0] = v.x; d[1] = v.y; d[2] = v.z; d[3] = v.w;
        }
        /* load Wa chunk: 16 rows x 64 = 256 float4, 8/thread */
        #pragma unroll
        for (int it = 0; it < 8; it++) {
            int idx = tid + 32 * it;
            int row = idx >> 4, c = idx & 15;
            int e = (row < 8) ? elo : ehi;
            int r = row & 7;
            float4 v = *(const float4*)(Wa + ((size_t)e * 8 + r) * D_IN + k0 + 4 * c);
            float* d = &ws[row * XS_STRIDE + 4 * c];
            d[0] = v.x; d[1] = v.y; d[2] = v.z; d[3] = v.w;
        }
        __syncwarp();

        #pragma unroll 4
        for (int k = 0; k < KCH; k++) {
            float wf[4];
            #pragma unroll
            for (int jj = 0; jj < 4; jj++)
                wf[jj] = ws[(jIdx * 4 + jj) * XS_STRIDE + k];
            #pragma unroll
            for (int i = 0; i < 8; i++) {
                float xv = xs[(tmIdx * 8 + i) * XS_STRIDE + k];
                #pragma unroll
                for (int jj = 0; jj < 4; jj++)
                    acc[i][jj] = fmaf(xv, wf[jj], acc[i][jj]);
            }
        }
        __syncwarp();
    }

    #pragma unroll
    for (int i = 0; i < 8; i++) {
        int row = tmIdx * 8 + i;
        if (row < cnt) {
            int t = toks[row];
            #pragma unroll
            for (int jj = 0; jj < 4; jj++)
                g_raw[split][t][jIdx * 4 + jj] = acc[i][jj];
        }
    }
}

/* ------------------------------ combine ----------------------------------- */
/* mid[t][r] = wA.x*raw[r] + wA.y*raw[8+r] (summed over splits); fold B wts   */
__global__ void __launch_bounds__(256) k_combine() {
    int gid = blockIdx.x * 256 + threadIdx.x;   /* 65536 = 8192*8 */
    int t = gid >> 3, r = gid & 7;
    float s0 = 0.0f, s1 = 0.0f;
    #pragma unroll
    for (int s = 0; s < SPLITS; s++) {
        s0 += g_raw[s][t][r];
        s1 += g_raw[s][t][8 + r];
    }
    float2 wa = g_wA[t];
    float mid = wa.x * s0 + wa.y * s1;
    float2 wb = g_wB[t];
    g_v[t][r]     = SCALING * wb.x * mid;
    g_v[t][8 + r] = SCALING * wb.y * mid;
}

/* ------------------------------ GEMM B ------------------------------------ */
/* grid (MAXT, 16). block (32,8). tile: 64 tokens x 256 outputs, K=16        */
__global__ void __launch_bounds__(256) k_gemmB(const float* __restrict__ Wb,
                                               float* __restrict__ out) {
    int tile = blockIdx.x;
    if (tile >= g_nTB) return;
    int p = g_tBp[tile], base = g_tBs[tile], cnt = g_tBc[tile];
    int elo = p >> 3, ehi = p & 7;
    int oBase = blockIdx.y * 256;

    __shared__ float ws[16 * 256];
    __shared__ float vsh[64 * 16];
    __shared__ int   toks[64];

    int tid = threadIdx.y * 32 + threadIdx.x;
    int lane = threadIdx.x, tId = threadIdx.y;

    if (tid < 64) toks[tid] = g_listB[base + ((tid < cnt) ? tid : 0)];
    __syncthreads();

    /* Wb slice: 2 experts x 256 rows x 8 r -> ws[k][o], k<8 = elo rows */
    #pragma unroll
    for (int it = 0; it < 4; it++) {
        int idx = tid + 256 * it;          /* 1024 float4 */
        int o  = idx & 255;
        int eh = idx >> 8;                 /* 0..3 */
        int e  = (eh >> 1) ? ehi : elo;
        int h  = eh & 1;
        float4 v = *(const float4*)(Wb + ((size_t)e * D_OUT + oBase + o) * 8 + 4 * h);
        int kb = (eh >> 1) * 8 + 4 * h;
        ws[(kb + 0) * 256 + o] = v.x;
        ws[(kb + 1) * 256 + o] = v.y;
        ws[(kb + 2) * 256 + o] = v.z;
        ws[(kb + 3) * 256 + o] = v.w;
    }
    /* v: 64 tokens x 16 = 256 float4 */
    {
        int idx = tid;
        int tok = idx >> 2, h = idx & 3;
        float4 v = *(const float4*)(&g_v[toks[tok]][4 * h]);
        *(float4*)(&vsh[tok * 16 + 4 * h]) = v;
    }
    __syncthreads();

    float acc[8][8];
    #pragma unroll
    for (int i = 0; i < 8; i++)
        #pragma unroll
        for (int j = 0; j < 8; j++) acc[i][j] = 0.0f;

    #pragma unroll
    for (int k = 0; k < 16; k++) {
        float wf[8];
        #pragma unroll
        for (int j = 0; j < 8; j++) wf[j] = ws[k * 256 + lane + 32 * j];
        #pragma unroll
        for (int i = 0; i < 8; i++) {
            float vv = vsh[(tId * 8 + i) * 16 + k];
            #pragma unroll
            for (int j = 0; j < 8; j++)
                acc[i][j] = fmaf(vv, wf[j], acc[i][j]);
        }
    }

    #pragma unroll
    for (int i = 0; i < 8; i++) {
        int row = tId * 8 + i;
        if (row < cnt) {
            int t = toks[row];
            float* od = out + (size_t)t * D_OUT + oBase + lane;
            #pragma unroll
            for (int j = 0; j < 8; j++)
                od[32 * j] = acc[i][j];
        }
    }
}

/* ------------------------------ launcher ---------------------------------- */
extern "C" void kernel_launch(void* const* d_in, const int* in_sizes, int n_in,
                              void* d_out, int out_size) {
    const float* x   = (const float*)d_in[0];
    const float* rla = (const float*)d_in[1];
    const float* rlb = (const float*)d_in[2];
    const float* Wa  = (const float*)d_in[3];
    const float* Wb  = (const float*)d_in[4];
    float* out = (float*)d_out;

    k_zero<<<1, 64>>>();
    k_route<<<RBLK, 256>>>(rla, rlb);
    k_plan<<<1, 128>>>(out, (long long)out_size);
    k_scatter<<<T_TOK / 256, 256>>>();
    k_gemmA<<<dim3(MAXT, SPLITS), 32>>>(x, Wa);
    k_combine<<<T_TOK * 8 / 256, 256>>>();
    k_gemmB<<<dim3(MAXT, 16), dim3(32, 8)>>>(Wb, out);
}

// round 11
// speedup vs baseline: 1.5745x; 1.5745x over previous
#include <cuda_runtime.h>
#include <math.h>
#include <stdint.h>

typedef unsigned long long ull;

#define T_TOK 8192
#define D_IN  4096
#define D_OUT 4096
#define NPAIR 64
#define SPLITS 8
#define KSPL  512
#define KCH   32
#define BM    64
#define MAXT  192
#define RBLK  32
#define SCALING 2.0f
#define XST   36          /* smem row stride (floats): 144B, 16B-aligned */

/* ------------------ static device scratch (no allocation) ------------------ */
__device__ int    g_pairA[T_TOK];
__device__ float2 g_wA[T_TOK];
__device__ int    g_pairB[T_TOK];
__device__ float2 g_wB[T_TOK];
__device__ int g_curA[NPAIR], g_curB[NPAIR];
__device__ int g_listA[T_TOK], g_listB[T_TOK];
__device__ int g_tAp[MAXT], g_tAs[MAXT], g_tAc[MAXT];
__device__ int g_tBp[MAXT], g_tBs[MAXT], g_tBc[MAXT];
__device__ int g_nTA, g_nTB;
__device__ float g_psA[RBLK][8];
__device__ float g_psB[RBLK][8];
__device__ __align__(16) float g_raw[SPLITS][T_TOK][16];
__device__ __align__(16) float g_v[T_TOK][16];

/* ------------------------------ helpers ------------------------------------ */
__device__ __forceinline__ uint32_t s2u(const void* p) {
    return (uint32_t)__cvta_generic_to_shared(p);
}
__device__ __forceinline__ void cp16(uint32_t dst, const float* src) {
    asm volatile("{\n .reg .u64 g;\n cvta.to.global.u64 g, %1;\n"
                 " cp.async.cg.shared.global [%0], [g], 16;\n}"
                 :: "r"(dst), "l"(src));
}
__device__ __forceinline__ float lo64(ull v) { return __uint_as_float((uint32_t)v); }
__device__ __forceinline__ float hi64(ull v) { return __uint_as_float((uint32_t)(v >> 32)); }
__device__ __forceinline__ ull dup32(float f) {
    uint32_t u = __float_as_uint(f);
    return ((ull)u << 32) | (ull)u;
}

/* ------------------------------- routing ---------------------------------- */
__device__ __forceinline__ void route_one(const float* __restrict__ lg, int t,
                                          int* pair, float2* w, float probs[8]) {
    const float4* p4 = (const float4*)lg + (size_t)t * 2;
    float4 a = p4[0], b = p4[1];
    float l[8] = {a.x, a.y, a.z, a.w, b.x, b.y, b.z, b.w};
    int i0 = 0; float v0 = l[0];
    #pragma unroll
    for (int i = 1; i < 8; i++) if (l[i] > v0) { v0 = l[i]; i0 = i; }
    int i1 = -1; float v1 = -3.0e38f;
    #pragma unroll
    for (int i = 0; i < 8; i++) if (i != i0 && l[i] > v1) { v1 = l[i]; i1 = i; }
    float e  = expf(v1 - v0);
    float w0 = 1.0f / (1.0f + e);
    float w1 = e * w0;
    int elo, ehi; float wlo, whi;
    if (i0 < i1) { elo = i0; ehi = i1; wlo = w0; whi = w1; }
    else         { elo = i1; ehi = i0; wlo = w1; whi = w0; }
    pair[t] = elo * 8 + ehi;
    w[t] = make_float2(wlo, whi);
    float s = 0.0f;
    #pragma unroll
    for (int i = 0; i < 8; i++) { probs[i] = expf(l[i] - v0); s += probs[i]; }
    float inv = 1.0f / s;
    #pragma unroll
    for (int i = 0; i < 8; i++) probs[i] *= inv;
}

__global__ void __launch_bounds__(256) k_route(const float* __restrict__ rla,
                                               const float* __restrict__ rlb) {
    int tid = threadIdx.x;
    int t = blockIdx.x * 256 + tid;
    float pa[8], pb[8];
    route_one(rla, t, g_pairA, g_wA, pa);
    route_one(rlb, t, g_pairB, g_wB, pb);

    __shared__ float sA[8][8], sB[8][8];
    int warp = tid >> 5, lane = tid & 31;
    #pragma unroll
    for (int e = 0; e < 8; e++) {
        float s = pa[e];
        #pragma unroll
        for (int o = 16; o > 0; o >>= 1) s += __shfl_xor_sync(0xffffffffu, s, o);
        if (lane == 0) sA[warp][e] = s;
        float s2 = pb[e];
        #pragma unroll
        for (int o = 16; o > 0; o >>= 1) s2 += __shfl_xor_sync(0xffffffffu, s2, o);
        if (lane == 0) sB[warp][e] = s2;
    }
    __syncthreads();
    if (tid < 8) {
        float s = 0.0f;
        #pragma unroll
        for (int w2 = 0; w2 < 8; w2++) s += sA[w2][tid];
        g_psA[blockIdx.x][tid] = s;
    } else if (tid < 16) {
        int e = tid - 8; float s = 0.0f;
        #pragma unroll
        for (int w2 = 0; w2 < 8; w2++) s += sB[w2][e];
        g_psB[blockIdx.x][e] = s;
    }
}

/* -------------------- plan: histogram + scan + tiles + aux ----------------- */
__global__ void __launch_bounds__(256) k_plan(float* __restrict__ out,
                                              long long out_size) {
    __shared__ int hA[NPAIR], hB[NPAIR];
    int tid = threadIdx.x;
    if (tid < NPAIR) { hA[tid] = 0; hB[tid] = 0; }
    __syncthreads();
    for (int i = tid; i < T_TOK; i += 256) {
        atomicAdd(&hA[g_pairA[i]], 1);
        atomicAdd(&hB[g_pairB[i]], 1);
    }
    __syncthreads();

    if (tid == 0) {
        int off = 0, nt = 0;
        for (int p = 0; p < NPAIR; p++) {
            int c = hA[p];
            g_curA[p] = off;
            int s = off;
            while (c > 0 && nt < MAXT) {
                g_tAp[nt] = p; g_tAs[nt] = s;
                g_tAc[nt] = (c < BM) ? c : BM;
                nt++; s += BM; c -= BM;
            }
            off += hA[p];
        }
        g_nTA = nt;
    }
    if (tid == 32) {
        int off = 0, nt = 0;
        for (int p = 0; p < NPAIR; p++) {
            int c = hB[p];
            g_curB[p] = off;
            int s = off;
            while (c > 0 && nt < MAXT) {
                g_tBp[nt] = p; g_tBs[nt] = s;
                g_tBc[nt] = (c < BM) ? c : BM;
                nt++; s += BM; c -= BM;
            }
            off += hB[p];
        }
        g_nTB = nt;
    }
    if (tid == 64 && out_size >= (long long)T_TOK * D_OUT + 2) {
        float pr[8];
        for (int e = 0; e < 8; e++) {
            float s = 0.0f;
            for (int b = 0; b < RBLK; b++) s += g_psA[b][e];
            pr[e] = s / (float)T_TOK;
        }
        float m = 0.0f;
        for (int e = 0; e < 8; e++) m += pr[e];
        m *= 0.125f;
        float v = 0.0f;
        for (int e = 0; e < 8; e++) { float d = pr[e] - m; v += d * d; }
        out[out_size - 2] = 8.0f * (v / 7.0f);
    }
    if (tid == 96 && out_size >= (long long)T_TOK * D_OUT + 2) {
        float pr[8];
        for (int e = 0; e < 8; e++) {
            float s = 0.0f;
            for (int b = 0; b < RBLK; b++) s += g_psB[b][e];
            pr[e] = s / (float)T_TOK;
        }
        float m = 0.0f;
        for (int e = 0; e < 8; e++) m += pr[e];
        m *= 0.125f;
        float v = 0.0f;
        for (int e = 0; e < 8; e++) { float d = pr[e] - m; v += d * d; }
        out[out_size - 1] = 8.0f * (v / 7.0f);
    }
}

/* ------------------------------ scatter ----------------------------------- */
__global__ void __launch_bounds__(256) k_scatter() {
    int t = blockIdx.x * 256 + threadIdx.x;
    int s1 = atomicAdd(&g_curA[g_pairA[t]], 1);
    g_listA[s1] = t;
    int s2 = atomicAdd(&g_curB[g_pairB[t]], 1);
    g_listB[s2] = t;
}

/* ------------------------------ GEMM A ------------------------------------ */
/* grid (MAXT, SPLITS), 32 threads; 64 tok x 16 rows, K split = 512,
   double-buffered cp.async, f32x2 packed FMA over k-pairs.                  */
__global__ void __launch_bounds__(32) k_gemmA(const float* __restrict__ x,
                                              const float* __restrict__ Wa) {
    int tile = blockIdx.x;
    if (tile >= g_nTA) return;
    int split = blockIdx.y;
    int p = g_tAp[tile], base = g_tAs[tile], cnt = g_tAc[tile];
    int elo = p >> 3, ehi = p & 7;

    __shared__ float xs[2][64 * XST];
    __shared__ float ws[2][16 * XST];
    __shared__ int   toks[64];

    int tid = threadIdx.x;
    toks[tid]      = g_listA[base + ((tid      < cnt) ? tid      : 0)];
    toks[tid + 32] = g_listA[base + ((tid + 32 < cnt) ? tid + 32 : 0)];
    __syncwarp();

    int rr = tid >> 3, cc = tid & 7;
    const float* xptr[16];
    #pragma unroll
    for (int it = 0; it < 16; it++)
        xptr[it] = x + (size_t)toks[rr + 4 * it] * D_IN + 4 * cc;
    const float* wptr[4];
    #pragma unroll
    for (int it = 0; it < 4; it++) {
        int row = rr + 4 * it;
        int e = (row < 8) ? elo : ehi;
        wptr[it] = Wa + ((size_t)e * 8 + (row & 7)) * D_IN + 4 * cc;
    }
    uint32_t dx = s2u(&xs[0][rr * XST + 4 * cc]);
    uint32_t dw = s2u(&ws[0][rr * XST + 4 * cc]);
    const uint32_t xbo = 64 * XST * 4, wbo = 16 * XST * 4;
    const uint32_t ro  = 4 * XST * 4;

    int kBase = split * KSPL;
    /* prologue: chunk 0 -> buf 0 */
    #pragma unroll
    for (int it = 0; it < 16; it++) cp16(dx + it * ro, xptr[it] + kBase);
    #pragma unroll
    for (int it = 0; it < 4; it++)  cp16(dw + it * ro, wptr[it] + kBase);
    asm volatile("cp.async.commit_group;\n" ::);

    ull acc2[8][4];
    #pragma unroll
    for (int i = 0; i < 8; i++)
        #pragma unroll
        for (int j = 0; j < 4; j++) acc2[i][j] = 0ull;

    int jIdx = tid & 3, tmIdx = tid >> 2;
    int xrow0 = tmIdx * 8, wrow0 = jIdx * 4;

    for (int ch = 0; ch < KSPL / KCH; ch++) {
        int buf = ch & 1;
        if (ch + 1 < KSPL / KCH) {
            int k0 = kBase + (ch + 1) * KCH;
            uint32_t bx = dx + (uint32_t)(buf ^ 1) * xbo;
            uint32_t bw = dw + (uint32_t)(buf ^ 1) * wbo;
            #pragma unroll
            for (int it = 0; it < 16; it++) cp16(bx + it * ro, xptr[it] + k0);
            #pragma unroll
            for (int it = 0; it < 4; it++)  cp16(bw + it * ro, wptr[it] + k0);
            asm volatile("cp.async.commit_group;\n" ::);
            asm volatile("cp.async.wait_group 1;\n" ::);
        } else {
            asm volatile("cp.async.wait_group 0;\n" ::);
        }
        __syncwarp();

        const float* xb = xs[buf];
        const float* wb = ws[buf];
        #pragma unroll
        for (int k = 0; k < KCH; k += 2) {
            ull w2[4];
            #pragma unroll
            for (int jj = 0; jj < 4; jj++)
                w2[jj] = *(const ull*)&wb[(wrow0 + jj) * XST + k];
            #pragma unroll
            for (int i = 0; i < 8; i++) {
                ull xv = *(const ull*)&xb[(xrow0 + i) * XST + k];
                #pragma unroll
                for (int jj = 0; jj < 4; jj++)
                    asm("fma.rn.f32x2 %0, %1, %2, %0;"
                        : "+l"(acc2[i][jj]) : "l"(xv), "l"(w2[jj]));
            }
        }
        __syncwarp();
    }

    #pragma unroll
    for (int i = 0; i < 8; i++) {
        int row = xrow0 + i;
        if (row < cnt) {
            int t = toks[row];
            float4 r;
            r.x = lo64(acc2[i][0]) + hi64(acc2[i][0]);
            r.y = lo64(acc2[i][1]) + hi64(acc2[i][1]);
            r.z = lo64(acc2[i][2]) + hi64(acc2[i][2]);
            r.w = lo64(acc2[i][3]) + hi64(acc2[i][3]);
            *(float4*)&g_raw[split][t][jIdx * 4] = r;
        }
    }
}

/* ------------------------------ combine ----------------------------------- */
__global__ void __launch_bounds__(256) k_combine() {
    int gid = blockIdx.x * 256 + threadIdx.x;   /* 65536 = 8192*8 */
    int t = gid >> 3, r = gid & 7;
    float s0 = 0.0f, s1 = 0.0f;
    #pragma unroll
    for (int s = 0; s < SPLITS; s++) {
        s0 += g_raw[s][t][r];
        s1 += g_raw[s][t][8 + r];
    }
    float2 wa = g_wA[t];
    float mid = wa.x * s0 + wa.y * s1;
    float2 wb = g_wB[t];
    g_v[t][r]     = SCALING * wb.x * mid;
    g_v[t][8 + r] = SCALING * wb.y * mid;
}

/* ------------------------------ GEMM B ------------------------------------ */
/* grid (MAXT, 16). block (32,8). 64 tok x 256 out, K=16.
   f32x2 packing over output-pairs; v duplicated into both halves.           */
__global__ void __launch_bounds__(256) k_gemmB(const float* __restrict__ Wb,
                                               float* __restrict__ out) {
    int tile = blockIdx.x;
    if (tile >= g_nTB) return;
    int p = g_tBp[tile], base = g_tBs[tile], cnt = g_tBc[tile];
    int elo = p >> 3, ehi = p & 7;
    int oBase = blockIdx.y * 256;

    __shared__ float ws[16 * 256];
    __shared__ ull   vshd[64 * 16];
    __shared__ int   toks[64];

    int tid = threadIdx.y * 32 + threadIdx.x;
    int lane = threadIdx.x, tId = threadIdx.y;

    if (tid < 64) toks[tid] = g_listB[base + ((tid < cnt) ? tid : 0)];
    __syncthreads();

    /* ws[k][o]: k = expert_half*8 + r */
    #pragma unroll
    for (int it = 0; it < 4; it++) {
        int idx = tid + 256 * it;
        int o = idx & 255, eh = idx >> 8;
        int e = (eh & 2) ? ehi : elo;
        int h = eh & 1;
        float4 v = *(const float4*)(Wb + ((size_t)e * D_OUT + oBase + o) * 8 + 4 * h);
        int kb = (eh >> 1) * 8 + 4 * h;
        ws[(kb + 0) * 256 + o] = v.x;
        ws[(kb + 1) * 256 + o] = v.y;
        ws[(kb + 2) * 256 + o] = v.z;
        ws[(kb + 3) * 256 + o] = v.w;
    }
    /* vshd[tok][k] = (v,v) packed */
    {
        int tok = tid >> 2, h = tid & 3;
        float4 v = *(const float4*)(&g_v[toks[tok]][4 * h]);
        ull* d = &vshd[tok * 16 + 4 * h];
        d[0] = dup32(v.x); d[1] = dup32(v.y); d[2] = dup32(v.z); d[3] = dup32(v.w);
    }
    __syncthreads();

    ull acc2[8][4];
    #pragma unroll
    for (int i = 0; i < 8; i++)
        #pragma unroll
        for (int j = 0; j < 4; j++) acc2[i][j] = 0ull;

    #pragma unroll
    for (int k = 0; k < 16; k++) {
        const float* wk = &ws[k * 256 + lane * 8];
        ull wp[4];
        wp[0] = *(const ull*)(wk + 0);
        wp[1] = *(const ull*)(wk + 2);
        wp[2] = *(const ull*)(wk + 4);
        wp[3] = *(const ull*)(wk + 6);
        #pragma unroll
        for (int i = 0; i < 8; i++) {
            ull vv = vshd[(tId * 8 + i) * 16 + k];
            #pragma unroll
            for (int j = 0; j < 4; j++)
                asm("fma.rn.f32x2 %0, %1, %2, %0;"
                    : "+l"(acc2[i][j]) : "l"(vv), "l"(wp[j]));
        }
    }

    #pragma unroll
    for (int i = 0; i < 8; i++) {
        int row = tId * 8 + i;
        if (row < cnt) {
            int t = toks[row];
            float* od = out + (size_t)t * D_OUT + oBase + lane * 8;
            float4 r0 = make_float4(lo64(acc2[i][0]), hi64(acc2[i][0]),
                                    lo64(acc2[i][1]), hi64(acc2[i][1]));
            float4 r1 = make_float4(lo64(acc2[i][2]), hi64(acc2[i][2]),
                                    lo64(acc2[i][3]), hi64(acc2[i][3]));
            *(float4*)od = r0;
            *(float4*)(od + 4) = r1;
        }
    }
}

/* ------------------------------ launcher ---------------------------------- */
extern "C" void kernel_launch(void* const* d_in, const int* in_sizes, int n_in,
                              void* d_out, int out_size) {
    const float* x   = (const float*)d_in[0];
    const float* rla = (const float*)d_in[1];
    const float* rlb = (const float*)d_in[2];
    const float* Wa  = (const float*)d_in[3];
    const float* Wb  = (const float*)d_in[4];
    float* out = (float*)d_out;

    k_route<<<RBLK, 256>>>(rla, rlb);
    k_plan<<<1, 256>>>(out, (long long)out_size);
    k_scatter<<<T_TOK / 256, 256>>>();
    k_gemmA<<<dim3(MAXT, SPLITS), 32>>>(x, Wa);
    k_combine<<<T_TOK * 8 / 256, 256>>>();
    k_gemmB<<<dim3(MAXT, 16), dim3(32, 8)>>>(Wb, out);
}

// round 14
// speedup vs baseline: 1.7329x; 1.1006x over previous
#include <cuda_runtime.h>
#include <math.h>
#include <stdint.h>

typedef unsigned long long ull;

#define T_TOK 8192
#define D_IN  4096
#define D_OUT 4096
#define NPAIR 64
#define SPLITS 8
#define KSPL  512
#define KCH   32
#define BM    64
#define MAXT  192
#define RBLK  32
#define SCALING 2.0f
#define XST   36          /* smem row stride (floats): 144B, 16B-aligned */

/* ------------------ static device scratch (no allocation) ------------------ */
__device__ int    g_pairA[T_TOK];
__device__ float2 g_wA[T_TOK];
__device__ int    g_pairB[T_TOK];
__device__ float2 g_wB[T_TOK];
__device__ int g_curA[NPAIR], g_curB[NPAIR];
__device__ int g_listA[T_TOK], g_listB[T_TOK];
__device__ int g_tAp[MAXT], g_tAs[MAXT], g_tAc[MAXT];
__device__ int g_tBp[MAXT], g_tBs[MAXT], g_tBc[MAXT];
__device__ int g_nTA, g_nTB;
__device__ float g_psA[RBLK][8];
__device__ float g_psB[RBLK][8];
__device__ __align__(16) float g_raw[SPLITS][T_TOK][16];
__device__ __align__(16) float g_v[T_TOK][16];

/* ------------------------------ helpers ------------------------------------ */
__device__ __forceinline__ uint32_t s2u(const void* p) {
    return (uint32_t)__cvta_generic_to_shared(p);
}
__device__ __forceinline__ void cp16(uint32_t dst, const float* src) {
    asm volatile("{\n .reg .u64 g;\n cvta.to.global.u64 g, %1;\n"
                 " cp.async.cg.shared.global [%0], [g], 16;\n}"
                 :: "r"(dst), "l"(src));
}
__device__ __forceinline__ float lo64(ull v) { return __uint_as_float((uint32_t)v); }
__device__ __forceinline__ float hi64(ull v) { return __uint_as_float((uint32_t)(v >> 32)); }
__device__ __forceinline__ ull dup32(float f) {
    uint32_t u = __float_as_uint(f);
    return ((ull)u << 32) | (ull)u;
}

/* ------------------------------- routing ---------------------------------- */
__device__ __forceinline__ void route_one(const float* __restrict__ lg, int t,
                                          int* pair, float2* w, float probs[8]) {
    const float4* p4 = (const float4*)lg + (size_t)t * 2;
    float4 a = p4[0], b = p4[1];
    float l[8] = {a.x, a.y, a.z, a.w, b.x, b.y, b.z, b.w};
    int i0 = 0; float v0 = l[0];
    #pragma unroll
    for (int i = 1; i < 8; i++) if (l[i] > v0) { v0 = l[i]; i0 = i; }
    int i1 = -1; float v1 = -3.0e38f;
    #pragma unroll
    for (int i = 0; i < 8; i++) if (i != i0 && l[i] > v1) { v1 = l[i]; i1 = i; }
    float e  = expf(v1 - v0);
    float w0 = 1.0f / (1.0f + e);
    float w1 = e * w0;
    int elo, ehi; float wlo, whi;
    if (i0 < i1) { elo = i0; ehi = i1; wlo = w0; whi = w1; }
    else         { elo = i1; ehi = i0; wlo = w1; whi = w0; }
    pair[t] = elo * 8 + ehi;
    w[t] = make_float2(wlo, whi);
    float s = 0.0f;
    #pragma unroll
    for (int i = 0; i < 8; i++) { probs[i] = expf(l[i] - v0); s += probs[i]; }
    float inv = 1.0f / s;
    #pragma unroll
    for (int i = 0; i < 8; i++) probs[i] *= inv;
}

__global__ void __launch_bounds__(256) k_route(const float* __restrict__ rla,
                                               const float* __restrict__ rlb) {
    int tid = threadIdx.x;
    int t = blockIdx.x * 256 + tid;
    float pa[8], pb[8];
    route_one(rla, t, g_pairA, g_wA, pa);
    route_one(rlb, t, g_pairB, g_wB, pb);

    __shared__ float sA[8][8], sB[8][8];
    int warp = tid >> 5, lane = tid & 31;
    #pragma unroll
    for (int e = 0; e < 8; e++) {
        float s = pa[e];
        #pragma unroll
        for (int o = 16; o > 0; o >>= 1) s += __shfl_xor_sync(0xffffffffu, s, o);
        if (lane == 0) sA[warp][e] = s;
        float s2 = pb[e];
        #pragma unroll
        for (int o = 16; o > 0; o >>= 1) s2 += __shfl_xor_sync(0xffffffffu, s2, o);
        if (lane == 0) sB[warp][e] = s2;
    }
    __syncthreads();
    if (tid < 8) {
        float s = 0.0f;
        #pragma unroll
        for (int w2 = 0; w2 < 8; w2++) s += sA[w2][tid];
        g_psA[blockIdx.x][tid] = s;
    } else if (tid < 16) {
        int e = tid - 8; float s = 0.0f;
        #pragma unroll
        for (int w2 = 0; w2 < 8; w2++) s += sB[w2][e];
        g_psB[blockIdx.x][e] = s;
    }
}

/* -------------------- plan: histogram + scan + tiles + aux ----------------- */
__global__ void __launch_bounds__(256) k_plan(float* __restrict__ out,
                                              long long out_size) {
    __shared__ int hA[NPAIR], hB[NPAIR];
    int tid = threadIdx.x;
    if (tid < NPAIR) { hA[tid] = 0; hB[tid] = 0; }
    __syncthreads();
    for (int i = tid; i < T_TOK; i += 256) {
        atomicAdd(&hA[g_pairA[i]], 1);
        atomicAdd(&hB[g_pairB[i]], 1);
    }
    __syncthreads();

    if (tid == 0) {
        int off = 0, nt = 0;
        for (int p = 0; p < NPAIR; p++) {
            int c = hA[p];
            g_curA[p] = off;
            int s = off;
            while (c > 0 && nt < MAXT) {
                g_tAp[nt] = p; g_tAs[nt] = s;
                g_tAc[nt] = (c < BM) ? c : BM;
                nt++; s += BM; c -= BM;
            }
            off += hA[p];
        }
        g_nTA = nt;
    }
    if (tid == 32) {
        int off = 0, nt = 0;
        for (int p = 0; p < NPAIR; p++) {
            int c = hB[p];
            g_curB[p] = off;
            int s = off;
            while (c > 0 && nt < MAXT) {
                g_tBp[nt] = p; g_tBs[nt] = s;
                g_tBc[nt] = (c < BM) ? c : BM;
                nt++; s += BM; c -= BM;
            }
            off += hB[p];
        }
        g_nTB = nt;
    }
    if (tid == 64 && out_size >= (long long)T_TOK * D_OUT + 2) {
        float pr[8];
        for (int e = 0; e < 8; e++) {
            float s = 0.0f;
            for (int b = 0; b < RBLK; b++) s += g_psA[b][e];
            pr[e] = s / (float)T_TOK;
        }
        float m = 0.0f;
        for (int e = 0; e < 8; e++) m += pr[e];
        m *= 0.125f;
        float v = 0.0f;
        for (int e = 0; e < 8; e++) { float d = pr[e] - m; v += d * d; }
        out[out_size - 2] = 8.0f * (v / 7.0f);
    }
    if (tid == 96 && out_size >= (long long)T_TOK * D_OUT + 2) {
        float pr[8];
        for (int e = 0; e < 8; e++) {
            float s = 0.0f;
            for (int b = 0; b < RBLK; b++) s += g_psB[b][e];
            pr[e] = s / (float)T_TOK;
        }
        float m = 0.0f;
        for (int e = 0; e < 8; e++) m += pr[e];
        m *= 0.125f;
        float v = 0.0f;
        for (int e = 0; e < 8; e++) { float d = pr[e] - m; v += d * d; }
        out[out_size - 1] = 8.0f * (v / 7.0f);
    }
}

/* ------------------------------ scatter ----------------------------------- */
__global__ void __launch_bounds__(256) k_scatter() {
    int t = blockIdx.x * 256 + threadIdx.x;
    int s1 = atomicAdd(&g_curA[g_pairA[t]], 1);
    g_listA[s1] = t;
    int s2 = atomicAdd(&g_curB[g_pairB[t]], 1);
    g_listB[s2] = t;
}

/* ------------------------------ GEMM A ------------------------------------ */
/* grid (MAXT, SPLITS), 64 threads (2 warps). tile 64 tok x 16 out, K=512
   split. Double-buffered cp.async; f32x2 packed over k-pairs.
   Per-thread: 4 tok x 4 out. 2x warps/SM vs R6 at identical smem.          */
__global__ void __launch_bounds__(64) k_gemmA(const float* __restrict__ x,
                                              const float* __restrict__ Wa) {
    int tile = blockIdx.x;
    if (tile >= g_nTA) return;
    int split = blockIdx.y;
    int p = g_tAp[tile], base = g_tAs[tile], cnt = g_tAc[tile];
    int elo = p >> 3, ehi = p & 7;

    __shared__ float xs[2][64 * XST];
    __shared__ float ws[2][16 * XST];
    __shared__ int   toks[64];

    int tid = threadIdx.x;
    toks[tid] = g_listA[base + ((tid < cnt) ? tid : 0)];
    __syncthreads();

    /* loader mapping: rr = tid>>3 (0..7), cc = tid&7 (float4 col) */
    int rr = tid >> 3, cc = tid & 7;
    const float* xptr[8];
    #pragma unroll
    for (int it = 0; it < 8; it++)
        xptr[it] = x + (size_t)toks[rr + 8 * it] * D_IN + 4 * cc;
    const float* wptr[2];
    #pragma unroll
    for (int it = 0; it < 2; it++) {
        int row = rr + 8 * it;
        int e = (row < 8) ? elo : ehi;
        wptr[it] = Wa + ((size_t)e * 8 + (row & 7)) * D_IN + 4 * cc;
    }
    uint32_t dx = s2u(&xs[0][rr * XST + 4 * cc]);
    uint32_t dw = s2u(&ws[0][rr * XST + 4 * cc]);
    const uint32_t xbo = 64 * XST * 4, wbo = 16 * XST * 4;
    const uint32_t ro  = 8 * XST * 4;

    int kBase = split * KSPL;
    #pragma unroll
    for (int it = 0; it < 8; it++) cp16(dx + it * ro, xptr[it] + kBase);
    #pragma unroll
    for (int it = 0; it < 2; it++) cp16(dw + it * ro, wptr[it] + kBase);
    asm volatile("cp.async.commit_group;\n" ::);

    ull acc2[4][4];
    #pragma unroll
    for (int i = 0; i < 4; i++)
        #pragma unroll
        for (int j = 0; j < 4; j++) acc2[i][j] = 0ull;

    /* compute mapping: jIdx = tid&3 (4 out-groups of 4), tg = tid>>2 (0..15,
       4 tokens each) */
    int jIdx = tid & 3, tg = tid >> 2;
    int xrow0 = tg * 4, wrow0 = jIdx * 4;

    for (int ch = 0; ch < KSPL / KCH; ch++) {
        int buf = ch & 1;
        if (ch + 1 < KSPL / KCH) {
            int k0 = kBase + (ch + 1) * KCH;
            uint32_t bx = dx + (uint32_t)(buf ^ 1) * xbo;
            uint32_t bw = dw + (uint32_t)(buf ^ 1) * wbo;
            #pragma unroll
            for (int it = 0; it < 8; it++) cp16(bx + it * ro, xptr[it] + k0);
            #pragma unroll
            for (int it = 0; it < 2; it++) cp16(bw + it * ro, wptr[it] + k0);
            asm volatile("cp.async.commit_group;\n" ::);
            asm volatile("cp.async.wait_group 1;\n" ::);
        } else {
            asm volatile("cp.async.wait_group 0;\n" ::);
        }
        __syncthreads();

        const float* xb = xs[buf];
        const float* wb = ws[buf];
        #pragma unroll
        for (int k = 0; k < KCH; k += 2) {
            ull w2[4];
            #pragma unroll
            for (int jj = 0; jj < 4; jj++)
                w2[jj] = *(const ull*)&wb[(wrow0 + jj) * XST + k];
            #pragma unroll
            for (int i = 0; i < 4; i++) {
                ull xv = *(const ull*)&xb[(xrow0 + i) * XST + k];
                #pragma unroll
                for (int jj = 0; jj < 4; jj++)
                    asm("fma.rn.f32x2 %0, %1, %2, %0;"
                        : "+l"(acc2[i][jj]) : "l"(xv), "l"(w2[jj]));
            }
        }
        __syncthreads();
    }

    #pragma unroll
    for (int i = 0; i < 4; i++) {
        int row = xrow0 + i;
        if (row < cnt) {
            int t = toks[row];
            float4 r;
            r.x = lo64(acc2[i][0]) + hi64(acc2[i][0]);
            r.y = lo64(acc2[i][1]) + hi64(acc2[i][1]);
            r.z = lo64(acc2[i][2]) + hi64(acc2[i][2]);
            r.w = lo64(acc2[i][3]) + hi64(acc2[i][3]);
            *(float4*)&g_raw[split][t][jIdx * 4] = r;
        }
    }
}

/* ------------------------------ combine ----------------------------------- */
__global__ void __launch_bounds__(256) k_combine() {
    int gid = blockIdx.x * 256 + threadIdx.x;   /* 65536 = 8192*8 */
    int t = gid >> 3, r = gid & 7;
    float s0 = 0.0f, s1 = 0.0f;
    #pragma unroll
    for (int s = 0; s < SPLITS; s++) {
        s0 += g_raw[s][t][r];
        s1 += g_raw[s][t][8 + r];
    }
    float2 wa = g_wA[t];
    float mid = wa.x * s0 + wa.y * s1;
    float2 wb = g_wB[t];
    g_v[t][r]     = SCALING * wb.x * mid;
    g_v[t][8 + r] = SCALING * wb.y * mid;
}

/* ------------------------------ GEMM B ------------------------------------ */
/* grid (MAXT, 16). block (32,8). 64 tok x 256 out, K=16.
   f32x2 over out-pairs at o = 2*lane + 64*jj -> lane-contiguous LDS.64
   (conflict-free) and contiguous 256B STG.64 bursts.                        */
__global__ void __launch_bounds__(256) k_gemmB(const float* __restrict__ Wb,
                                               float* __restrict__ out) {
    int tile = blockIdx.x;
    if (tile >= g_nTB) return;
    int p = g_tBp[tile], base = g_tBs[tile], cnt = g_tBc[tile];
    int elo = p >> 3, ehi = p & 7;
    int oBase = blockIdx.y * 256;

    __shared__ float ws[16 * 256];
    __shared__ ull   vshd[64 * 16];
    __shared__ int   toks[64];

    int tid = threadIdx.y * 32 + threadIdx.x;
    int lane = threadIdx.x, tId = threadIdx.y;

    if (tid < 64) toks[tid] = g_listB[base + ((tid < cnt) ? tid : 0)];
    __syncthreads();

    /* ws[k][o]: k = expert_half*8 + r */
    #pragma unroll
    for (int it = 0; it < 4; it++) {
        int idx = tid + 256 * it;
        int o = idx & 255, eh = idx >> 8;
        int e = (eh & 2) ? ehi : elo;
        int h = eh & 1;
        float4 v = *(const float4*)(Wb + ((size_t)e * D_OUT + oBase + o) * 8 + 4 * h);
        int kb = (eh >> 1) * 8 + 4 * h;
        ws[(kb + 0) * 256 + o] = v.x;
        ws[(kb + 1) * 256 + o] = v.y;
        ws[(kb + 2) * 256 + o] = v.z;
        ws[(kb + 3) * 256 + o] = v.w;
    }
    /* vshd[tok][k] = (v,v) packed */
    {
        int tok = tid >> 2, h = tid & 3;
        float4 v = *(const float4*)(&g_v[toks[tok]][4 * h]);
        ull* d = &vshd[tok * 16 + 4 * h];
        d[0] = dup32(v.x); d[1] = dup32(v.y); d[2] = dup32(v.z); d[3] = dup32(v.w);
    }
    __syncthreads();

    ull acc2[8][4];
    #pragma unroll
    for (int i = 0; i < 8; i++)
        #pragma unroll
        for (int j = 0; j < 4; j++) acc2[i][j] = 0ull;

    #pragma unroll
    for (int k = 0; k < 16; k++) {
        ull wp[4];
        #pragma unroll
        for (int jj = 0; jj < 4; jj++)
            wp[jj] = *(const ull*)&ws[k * 256 + 2 * lane + 64 * jj];
        #pragma unroll
        for (int i = 0; i < 8; i++) {
            ull vv = vshd[(tId * 8 + i) * 16 + k];
            #pragma unroll
            for (int jj = 0; jj < 4; jj++)
                asm("fma.rn.f32x2 %0, %1, %2, %0;"
                    : "+l"(acc2[i][jj]) : "l"(vv), "l"(wp[jj]));
        }
    }

    #pragma unroll
    for (int i = 0; i < 8; i++) {
        int row = tId * 8 + i;
        if (row < cnt) {
            int t = toks[row];
            float* od = out + (size_t)t * D_OUT + oBase + 2 * lane;
            #pragma unroll
            for (int jj = 0; jj < 4; jj++) {
                float2 r = make_float2(lo64(acc2[i][jj]), hi64(acc2[i][jj]));
                *(float2*)(od + 64 * jj) = r;
            }
        }
    }
}

/* ------------------------------ launcher ---------------------------------- */
extern "C" void kernel_launch(void* const* d_in, const int* in_sizes, int n_in,
                              void* d_out, int out_size) {
    const float* x   = (const float*)d_in[0];
    const float* rla = (const float*)d_in[1];
    const float* rlb = (const float*)d_in[2];
    const float* Wa  = (const float*)d_in[3];
    const float* Wb  = (const float*)d_in[4];
    float* out = (float*)d_out;

    k_route<<<RBLK, 256>>>(rla, rlb);
    k_plan<<<1, 256>>>(out, (long long)out_size);
    k_scatter<<<T_TOK / 256, 256>>>();
    k_gemmA<<<dim3(MAXT, SPLITS), 64>>>(x, Wa);
    k_combine<<<T_TOK * 8 / 256, 256>>>();
    k_gemmB<<<dim3(MAXT, 16), dim3(32, 8)>>>(Wb, out);
}